// round 4
// baseline (speedup 1.0000x reference)
#include <cuda_runtime.h>

// SINDy library: out[row] = [1, z(32), z_i*z_j (528), z_a*z_b*z_c (5984), sin(z)(32)]
// 8192 rows x 6577 cols fp32. value(col) = s_mul[a] * s_buf[k].
// R4: 4 rows/block (table amortization + ILP), 2 shifted s_buf copies + LDS.64 pairs,
//     float4 stores with per-row-phase group tables.

#define NDIM     32
#define NPAIRS   528
#define NCOLS    6577
#define SBUF_PAD 600           // >= 593 + shift, multiple of 4
#define MAXG     1645
#define RPB      4             // rows per block
#define GRID     2048          // 8192 / RPB

static constexpr int pair_index(int i, int j) {
    return i * NDIM - (i * (i - 1)) / 2 + (j - i);
}

struct ColTbl  { unsigned short e[NCOLS]; };   // per column: k | (a<<10)
struct GrpTbl  { unsigned int   e[4][MAXG]; }; // per phase/group: k0 | (a<<10); bit31 = boundary
struct PairTbl { unsigned short e[NPAIRS]; };  // i | (j<<8)

static constexpr ColTbl make_col_tbl() {
    ColTbl t{};
    for (int c = 0; c < 561; ++c)                       // 1, z, pairs: k=c, a=32(=1.0)
        t.e[c] = (unsigned short)((unsigned)c | (32u << 10));
    {
        int col = 561;                                  // triples
        for (int a = 0; a < NDIM; ++a)
            for (int b = a; b < NDIM; ++b)
                for (int c = b; c < NDIM; ++c) {
                    unsigned k = 33u + (unsigned)pair_index(b, c);
                    t.e[col++] = (unsigned short)(k | ((unsigned)a << 10));
                }
    }
    for (int i = 0; i < NDIM; ++i)                      // sin
        t.e[6545 + i] = (unsigned short)((unsigned)(561 + i) | (32u << 10));
    return t;
}
__device__ constexpr ColTbl G_COL = make_col_tbl();

static constexpr GrpTbl make_grp_tbl() {
    ColTbl ct = make_col_tbl();
    GrpTbl g{};
    for (int p = 0; p < 4; ++p) {
        int ng = (NCOLS - p) / 4;
        for (int gi = 0; gi < ng; ++gi) {
            int c0 = p + 4 * gi;
            unsigned k0 = ct.e[c0] & 1023u;
            unsigned a0 = (unsigned)(ct.e[c0] >> 10);
            bool uniform = true;
            for (int j = 1; j < 4; ++j) {
                unsigned kj = ct.e[c0 + j] & 1023u;
                unsigned aj = (unsigned)(ct.e[c0 + j] >> 10);
                if (kj != k0 + (unsigned)j || aj != a0) { uniform = false; break; }
            }
            g.e[p][gi] = uniform ? (k0 | (a0 << 10)) : 0x80000000u;
        }
    }
    return g;
}
__device__ constexpr GrpTbl G_GRP = make_grp_tbl();

static constexpr PairTbl make_pair_tbl() {
    PairTbl t{};
    int p = 0;
    for (int i = 0; i < NDIM; ++i)
        for (int j = i; j < NDIM; ++j)
            t.e[p++] = (unsigned short)((unsigned)i | ((unsigned)j << 8));
    return t;
}
__device__ constexpr PairTbl G_PAIR = make_pair_tbl();

__global__ __launch_bounds__(256) void sindy_library_kernel(
    const float* __restrict__ z, float* __restrict__ out)
{
    // Per row: two shifted copies. s_copy[r][P][P + k] = buf[k], P = k & 1,
    // so float2 reads at (k0 + P) are 8B-aligned when P = k0 & 1.
    __shared__ __align__(16) float s_copy[RPB][2][SBUF_PAD];
    __shared__ float s_mul[RPB][NDIM + 1];

    const int b = blockIdx.x;
    const int t = threadIdx.x;

    // Build z / sin / 1 for all RPB rows
    if (t < RPB * NDIM) {
        int r = t >> 5, i = t & 31;
        int row = b + r * GRID;
        float v = z[row * NDIM + i];
        float sv = __sinf(v);
        s_mul[r][i] = v;
        #pragma unroll
        for (int P = 0; P < 2; ++P) {
            s_copy[r][P][P + 1 + i]   = v;
            s_copy[r][P][P + 561 + i] = sv;
        }
    } else if (t < RPB * NDIM + RPB) {
        int r = t - RPB * NDIM;
        s_mul[r][NDIM] = 1.0f;
        s_copy[r][0][0] = 1.0f;
        s_copy[r][1][1] = 1.0f;
    }
    __syncthreads();

    // Pair products for all rows into both copies
    #pragma unroll
    for (int p = t; p < NPAIRS; p += 256) {
        unsigned ij = (unsigned)G_PAIR.e[p];
        unsigned i = ij & 31u, j = (ij >> 8) & 31u;
        #pragma unroll
        for (int r = 0; r < RPB; ++r) {
            float v = s_mul[r][i] * s_mul[r][j];
            s_copy[r][0][33 + p]     = v;
            s_copy[r][1][1 + 33 + p] = v;
        }
    }
    __syncthreads();

    float* o[RPB];
    #pragma unroll
    for (int r = 0; r < RPB; ++r)
        o[r] = out + (size_t)(b + r * GRID) * NCOLS;

    // All RPB rows share the same phase (rows differ by multiples of GRID=2048, 2048%4==0)
    const int ph = (4 - (b & 3)) & 3;

    if (t < ph) {                       // head (<4 scalar cols per row)
        unsigned e = (unsigned)G_COL.e[t];
        unsigned k = e & 1023u, a = e >> 10;
        #pragma unroll
        for (int r = 0; r < RPB; ++r)
            o[r][t] = s_mul[r][a] * s_copy[r][0][k];
    }

    const int ng = (NCOLS - ph) >> 2;
    for (int g = t; g < ng; g += 256) {
        const int c0 = ph + (g << 2);
        unsigned e = __ldg(&G_GRP.e[ph][g]);
        if ((int)e >= 0) {
            unsigned k0 = e & 1023u;
            unsigned a  = (e >> 10) & 63u;
            unsigned P  = k0 & 1u;
            unsigned idx = k0 + P;     // 8B-aligned index into copy P
            #pragma unroll
            for (int r = 0; r < RPB; ++r) {
                float  za = s_mul[r][a];
                float2 b0 = *(const float2*)&s_copy[r][P][idx];
                float2 b1 = *(const float2*)&s_copy[r][P][idx + 2];
                *(float4*)(o[r] + c0) =
                    make_float4(za * b0.x, za * b0.y, za * b1.x, za * b1.y);
            }
        } else {
            unsigned e0 = (unsigned)G_COL.e[c0];
            unsigned e1 = (unsigned)G_COL.e[c0 + 1];
            unsigned e2 = (unsigned)G_COL.e[c0 + 2];
            unsigned e3 = (unsigned)G_COL.e[c0 + 3];
            #pragma unroll
            for (int r = 0; r < RPB; ++r) {
                float v0 = s_mul[r][e0 >> 10] * s_copy[r][0][e0 & 1023u];
                float v1 = s_mul[r][e1 >> 10] * s_copy[r][0][e1 & 1023u];
                float v2 = s_mul[r][e2 >> 10] * s_copy[r][0][e2 & 1023u];
                float v3 = s_mul[r][e3 >> 10] * s_copy[r][0][e3 & 1023u];
                *(float4*)(o[r] + c0) = make_float4(v0, v1, v2, v3);
            }
        }
    }

    {                                   // tail (<4 scalar cols per row)
        int c = ph + (ng << 2) + t;
        if (c < NCOLS) {
            unsigned e = (unsigned)G_COL.e[c];
            unsigned k = e & 1023u, a = e >> 10;
            #pragma unroll
            for (int r = 0; r < RPB; ++r)
                o[r][c] = s_mul[r][a] * s_copy[r][0][k];
        }
    }
}

extern "C" void kernel_launch(void* const* d_in, const int* in_sizes, int n_in,
                              void* d_out, int out_size) {
    const float* z   = (const float*)d_in[0];
    float*       out = (float*)d_out;
    sindy_library_kernel<<<GRID, 256>>>(z, out);
}